// round 10
// baseline (speedup 1.0000x reference)
#include <cuda_runtime.h>
#include <math.h>
#include <stdint.h>

// ---------------- constants ----------------
#define NTc 256
// dup-pair strides (in float2/u64 elements):
//   phase1: XP2=160 (X/SKIP), GP2=136 ; phase2: XP2=288, GP2=264
// refine: 264 pairs/row, 136 rows (4 c-guards each side), per-channel pairs:
#define RROW 264
#define RCHP 35904           // 136*264 pairs per refine channel

__device__ __constant__ int c_DILS[15] = {1,2,3,4,6,8,10,12,14,16,18,20,24,28,32};

// ---------------- scratch (dup-pair layouts) ----------------
__device__ float g_X[1310720];    // [H][16][XP2] pairs
__device__ float g_SKIP[1310720]; // same layout as X
__device__ float g_G[557056];     // [H][8][GP2] pairs
__device__ float g_R2[524288];    // [f(16)][m(128)][t(256)] scalar
__device__ float g_HINP[524288];  // [c(128)][f(16)][t(256)] scalar
__device__ float g_HFT[1048576];  // [g(32)][c(128)][u(256)] scalar
__device__ float g_RA[4595712];   // refine ping [ch(64)][row(136)][RROW pairs]
__device__ float g_RB[4595712];   // refine pong
__device__ unsigned g_FN;
__device__ unsigned g_barcnt;

__device__ __forceinline__ float dfh_tanh(float x){ return tanhf(x)*0.98f + 0.02f*x; }
__device__ __forceinline__ float dfh_sig (float x){ return 0.98f/(1.0f+expf(-x)) + 0.02f*x; }

// ---------------- packed f32x2 helpers ----------------
__device__ __forceinline__ void fma2(uint64_t &d, uint64_t a, uint64_t b){
    asm("fma.rn.f32x2 %0, %1, %2, %0;" : "+l"(d) : "l"(a), "l"(b));
}
__device__ __forceinline__ uint64_t add2(uint64_t a, uint64_t b){
    uint64_t r; asm("add.rn.f32x2 %0, %1, %2;" : "=l"(r) : "l"(a), "l"(b)); return r;
}
__device__ __forceinline__ uint64_t pack2(float x){
    uint64_t r; asm("mov.b64 %0, {%1, %1};" : "=l"(r) : "f"(x)); return r;
}
__device__ __forceinline__ float2 unpack2(uint64_t v){
    float2 f; asm("mov.b64 {%0, %1}, %2;" : "=f"(f.x), "=f"(f.y) : "l"(v)); return f;
}

// ---------------- grid barrier (256 blocks resident via __launch_bounds__(256,2)) ----------------
__device__ __forceinline__ void gridbar(unsigned &target)
{
    __syncthreads();
    target += 256u;
    if (threadIdx.x == 0) {
        __threadfence();
        atomicAdd(&g_barcnt, 1u);
        while (*((volatile unsigned*)&g_barcnt) < target) { }
        __threadfence();
    }
    __syncthreads();
}

// ---------------- zero helpers ----------------
__global__ void k_zero3()
{
    if (blockIdx.x == 0 && threadIdx.x == 0) g_barcnt = 0u;
    int stride = gridDim.x*blockDim.x;
    for (int i = blockIdx.x*blockDim.x + threadIdx.x; i < 1310720; i += stride) {
        g_X[i] = 0.0f; g_SKIP[i] = 0.0f;
        if (i < 557056) g_G[i] = 0.0f;
    }
}
__global__ void k_zeroref()
{
    int stride = gridDim.x*blockDim.x;
    for (int i = blockIdx.x*blockDim.x + threadIdx.x; i < 4595712; i += stride) {
        g_RA[i] = 0.0f; g_RB[i] = 0.0f;
    }
}

// ---------------- input dense (4->16), dup store ----------------
__global__ void k_dense1(const float* __restrict__ inc, const float* __restrict__ icc,
                         const float* __restrict__ times, const float* __restrict__ tin,
                         const float* __restrict__ cw, const float* __restrict__ cb)
{
    int t = blockIdx.x, c = threadIdx.x;  // 256 x 128
    float i0 = inc[c*NTc + t];
    float i1 = icc[c*NTc + t];
    float i2 = times[t];
    float i3 = tin[c];
    #pragma unroll
    for (int o = 0; o < 16; ++o) {
        float v = i0*cw[o] + i1*cw[16+o] + i2*cw[32+o] + i3*cw[48+o] + cb[o];
        float a = dfh_tanh(v);
        ((float2*)g_X)[(t*16+o)*160 + c] = make_float2(a, a);
    }
}

// ---------------- PERSISTENT wave stack (dup-pair activations) ----------------
template<int H, int W, int XP2, int GP2>
__global__ __launch_bounds__(256,2) void k_wave_all(
    const float* __restrict__ wy1a, const float* __restrict__ by1a,
    const float* __restrict__ wy2a, const float* __restrict__ by2a,
    const float* __restrict__ wza,  const float* __restrict__ bza)
{
    constexpr int CHUNKS = W >> 5;
    constexpr int RPB    = 8 / CHUNKS;
    __shared__ float4 sW[1280];   // 20KB
    int tidx = threadIdx.x;
    int lane = tidx & 31, warp = tidx >> 5;
    int r = warp / CHUNKS, q = warp - r*CHUNKS;
    int w = (q << 5) + lane;
    int half = blockIdx.x & 1;
    int pb   = blockIdx.x >> 1;
    int h = pb * RPB + r;
    unsigned target = 0;

    for (int layer = 0; layer < 45; ++layer) {
        int dil = c_DILS[layer % 15];

        // ======== phase 1: gated conv pair (16ch -> 4+4 outs) ========
        {
            const float* w1g = wy1a + layer*5120;
            const float* w2g = wy2a + layer*5120;
            const float* b1  = by1a + layer*8;
            const float* b2  = by2a + layer*8;
            int o0 = half*4;
            for (int i = tidx; i < 1280; i += 256) {
                int tap = i >> 5, ci = (i >> 1) & 15, which = i & 1;
                const float* src = (which ? w2g : w1g) + tap*128 + ci*8 + o0;
                sW[i] = *(const float4*)src;
            }
            __syncthreads();

            uint64_t accA[4] = {0,0,0,0};
            uint64_t accB[4] = {0,0,0,0};

            for (int kh = 0; kh < 5; ++kh) {
                int hh = h + kh - 2;
                if ((unsigned)hh >= (unsigned)H) continue;
                const uint64_t* xrow = (const uint64_t*)g_X + hh*16*XP2;
                for (int kw = 0; kw < 8; ++kw) {
                    int cb0 = (q << 5) + kw*dil;
                    if (cb0 >= W) break;               // warp-uniform
                    const uint64_t* xp = xrow + cb0 + lane;
                    const ulonglong2* wp = (const ulonglong2*)(sW + (kh*8+kw)*32);
                    uint64_t xs[16];
                    #pragma unroll
                    for (int ci = 0; ci < 16; ++ci) xs[ci] = xp[ci*XP2];
                    #pragma unroll
                    for (int ci = 0; ci < 8; ++ci) {
                        ulonglong2 wv1 = wp[2*ci];
                        ulonglong2 wv2 = wp[2*ci+1];
                        fma2(accA[0], xs[ci], wv1.x); fma2(accA[1], xs[ci], wv1.y);
                        fma2(accA[2], xs[ci], wv2.x); fma2(accA[3], xs[ci], wv2.y);
                    }
                    #pragma unroll
                    for (int ci = 8; ci < 16; ++ci) {
                        ulonglong2 wv1 = wp[2*ci];
                        ulonglong2 wv2 = wp[2*ci+1];
                        fma2(accB[0], xs[ci], wv1.x); fma2(accB[1], xs[ci], wv1.y);
                        fma2(accB[2], xs[ci], wv2.x); fma2(accB[3], xs[ci], wv2.y);
                    }
                }
            }
            float y1[4], y2[4];
            {
                float2 a0 = unpack2(accA[0]), b0 = unpack2(accB[0]);
                float2 a1 = unpack2(accA[1]), b1v = unpack2(accB[1]);
                y1[0]=a0.x+b0.x; y1[1]=a0.y+b0.y; y1[2]=a1.x+b1v.x; y1[3]=a1.y+b1v.y;
                float2 a2 = unpack2(accA[2]), b2v = unpack2(accB[2]);
                float2 a3 = unpack2(accA[3]), b3 = unpack2(accB[3]);
                y2[0]=a2.x+b2v.x; y2[1]=a2.y+b2v.y; y2[2]=a3.x+b3.x; y2[3]=a3.y+b3.y;
            }
            #pragma unroll
            for (int j = 0; j < 4; ++j) {
                int oo = o0 + j;
                float g = dfh_tanh(y1[j] + __ldg(b1+oo)) * dfh_sig(y2[j] + __ldg(b2+oo));
                ((float2*)g_G)[(h*8+oo)*GP2 + w] = make_float2(g, g);
            }
        }
        gridbar(target);

        // ======== phase 2: z conv (8ch -> 8 of 16 outs) ========
        {
            const float* wzg = wza + layer*5120;
            const float* bz  = bza + layer*16;
            int o0 = half * 8;
            for (int i = tidx; i < 640; i += 256) {
                int tap = i >> 4, ci = (i >> 1) & 7, part = i & 1;
                sW[i] = *(const float4*)(wzg + tap*128 + ci*16 + o0 + part*4);
            }
            __syncthreads();

            uint64_t accA[4] = {0,0,0,0};
            uint64_t accB[4] = {0,0,0,0};

            for (int kh = 0; kh < 5; ++kh) {
                int hh = h + kh - 2;
                if ((unsigned)hh >= (unsigned)H) continue;
                const uint64_t* grow = (const uint64_t*)g_G + hh*8*GP2 + w;
                #pragma unroll
                for (int kw = 0; kw < 8; ++kw) {
                    const uint64_t* xp = grow + kw;           // zero pad: no guard
                    const ulonglong2* wp = (const ulonglong2*)(sW + (kh*8+kw)*16);
                    uint64_t xs[8];
                    #pragma unroll
                    for (int ci = 0; ci < 8; ++ci) xs[ci] = xp[ci*GP2];
                    #pragma unroll
                    for (int ci = 0; ci < 4; ++ci) {
                        ulonglong2 w01 = wp[2*ci];
                        ulonglong2 w23 = wp[2*ci+1];
                        fma2(accA[0], xs[ci], w01.x); fma2(accA[1], xs[ci], w01.y);
                        fma2(accA[2], xs[ci], w23.x); fma2(accA[3], xs[ci], w23.y);
                    }
                    #pragma unroll
                    for (int ci = 4; ci < 8; ++ci) {
                        ulonglong2 w01 = wp[2*ci];
                        ulonglong2 w23 = wp[2*ci+1];
                        fma2(accB[0], xs[ci], w01.x); fma2(accB[1], xs[ci], w01.y);
                        fma2(accB[2], xs[ci], w23.x); fma2(accB[3], xs[ci], w23.y);
                    }
                }
            }
            uint64_t* X2 = (uint64_t*)g_X;
            uint64_t* S2 = (uint64_t*)g_SKIP;
            #pragma unroll
            for (int p = 0; p < 4; ++p) {
                float2 va = unpack2(accA[p]);
                float2 vb = unpack2(accB[p]);
                int oo = o0 + 2*p;
                float z0 = va.x + vb.x + __ldg(bz+oo);
                float z1 = va.y + vb.y + __ldg(bz+oo+1);
                int idx0 = (h*16+oo)*XP2 + w;
                int idx1 = idx0 + XP2;
                uint64_t zz0 = pack2(z0), zz1 = pack2(z1);
                S2[idx0] = add2(S2[idx0], zz0);  X2[idx0] = add2(X2[idx0], zz0);
                S2[idx1] = add2(S2[idx1], zz1);  X2[idx1] = add2(X2[idx1], zz1);
            }
        }
        gridbar(target);
    }
}

// ---------------- stage C1 (SKIP dup layout: stride 320 floats, pair index 4k) ----------------
__global__ void k_c1()
{
    int t = blockIdx.x, f = blockIdx.y;     // 256 x 16
    __shared__ float vr[64], vi[64], tc[128], ts[128];
    int tid = threadIdx.x;                  // 128
    if (tid < 64) {
        int k = tid;
        float cr = g_SKIP[(t*16+f)*320 + 4*k];
        float ci = g_SKIP[(t*16+f)*320 + 4*k+2];
        cr = dfh_tanh(cr); ci = dfh_tanh(ci);
        float s = ((k==0)?0.5f:1.0f) * ((k&1)?-1.0f:1.0f);
        vr[k] = s*cr; vi[k] = s*ci;
    }
    {
        float sv, cv; sincospif((float)tid * (1.0f/64.0f), &sv, &cv);
        tc[tid] = cv; ts[tid] = sv;
    }
    __syncthreads();
    int m = tid;
    float acc = 0.0f;
    #pragma unroll 8
    for (int k = 0; k < 64; ++k) {
        int j = (k*m) & 127;
        acc += vr[k]*tc[j] + vi[k]*ts[j];
    }
    g_R2[(f*128+m)*NTc + t] = acc;
}

// ---------------- stage C2 ----------------
__global__ void k_c2(const float* __restrict__ times)
{
    int m = blockIdx.x, f = blockIdx.y;     // 128 x 16
    __shared__ float v[256], tc[256], ts[256];
    int tid = threadIdx.x;                  // 128
    v[tid]       = g_R2[(f*128+m)*NTc + tid];
    v[tid+128]   = g_R2[(f*128+m)*NTc + tid + 128];
    {
        float sv, cv;
        sincospif((float)tid * (1.0f/128.0f), &sv, &cv);        tc[tid] = cv;      ts[tid] = sv;
        sincospif((float)(tid+128) * (1.0f/128.0f), &sv, &cv);  tc[tid+128] = cv;  ts[tid+128] = sv;
    }
    __syncthreads();
    int k = tid;
    float zm = (k==0) ? 1.0f : ((fabsf(times[2*k]) > 0.0f) ? 1.0f : 0.0f);
    float scale = zm * ((k&1)?-1.0f:1.0f) * (1.0f/128.0f);
    float ar = 0.0f, ai = 0.0f;
    #pragma unroll 8
    for (int t = 0; t < 256; ++t) {
        int j = (t*k) & 255;
        ar += v[t]*tc[j];
        ai += v[t]*ts[j];
    }
    g_HINP[(m*16+f)*NTc + 2*k]   = scale*ar;
    g_HINP[(m*16+f)*NTc + 2*k+1] = scale*ai;
}

// ---------------- dense2 (16->16), dup store (phase2 XP2=288) ----------------
__global__ void k_dense2(const float* __restrict__ hw, const float* __restrict__ hb)
{
    int c = blockIdx.x;       // 128
    int t = threadIdx.x;      // 256
    float in[16];
    #pragma unroll
    for (int f = 0; f < 16; ++f) in[f] = g_HINP[(c*16+f)*NTc + t];
    #pragma unroll
    for (int o = 0; o < 16; ++o) {
        float acc = hb[o];
        #pragma unroll
        for (int f = 0; f < 16; ++f) acc += in[f]*hw[f*16+o];
        float a = dfh_tanh(acc);
        ((float2*)g_X)[(c*16+o)*288 + t] = make_float2(a, a);
    }
}

// ---------------- stage D (SKIP dup stride 576, pair index 4j) ----------------
__global__ void k_stageD()
{
    int c = blockIdx.x, g = blockIdx.y;     // 128 x 32
    __shared__ float hr[128], hi[128], tc[256], ts[256];
    int tid = threadIdx.x;                  // 256
    if (tid < 128) {
        int j = tid;
        float v0, v1;
        if (g < 16) {
            float a = g_SKIP[(c*16+g)*576 + 4*j];   v0 = dfh_tanh(a);
            float b = g_SKIP[(c*16+g)*576 + 4*j+2]; v1 = dfh_tanh(b);
        } else {
            v0 = g_HINP[(c*16+(g-16))*NTc + 2*j];
            v1 = g_HINP[(c*16+(g-16))*NTc + 2*j+1];
        }
        float s = ((j==0)?0.5f:1.0f) * ((j&1)?-1.0f:1.0f);
        hr[j] = s*v0; hi[j] = s*v1;
    }
    {
        float sv, cv; sincospif((float)tid * (1.0f/128.0f), &sv, &cv);
        tc[tid] = cv; ts[tid] = sv;
    }
    __syncthreads();
    int u = tid;
    float acc = 0.0f;
    #pragma unroll 8
    for (int j = 0; j < 128; ++j) {
        int idx = (j*u) & 255;
        acc += hr[j]*tc[idx] + hi[j]*ts[idx];
    }
    g_HFT[(g*128+c)*NTc + u] = acc;
}

// ---------------- fnorm ----------------
__global__ void k_fninit(){ g_FN = 0u; }

__global__ void k_fnred()
{
    int stride = gridDim.x*blockDim.x;
    float mx = 0.0f;
    for (int i = blockIdx.x*blockDim.x + threadIdx.x; i < 1048576; i += stride)
        mx = fmaxf(mx, fabsf(g_HFT[i]));
    #pragma unroll
    for (int o = 16; o; o >>= 1) mx = fmaxf(mx, __shfl_xor_sync(0xFFFFFFFFu, mx, o));
    __shared__ float sm[8];
    int lane = threadIdx.x & 31, warp = threadIdx.x >> 5;
    if (lane == 0) sm[warp] = mx;
    __syncthreads();
    if (warp == 0) {
        mx = (lane < 8) ? sm[lane] : 0.0f;
        #pragma unroll
        for (int o = 4; o; o >>= 1) mx = fmaxf(mx, __shfl_xor_sync(0xFFFFFFFFu, mx, o));
        if (lane == 0) atomicMax(&g_FN, __float_as_uint(mx));
    }
}

__global__ void k_refinit()
{
    float inv = 1.0f/__uint_as_float(g_FN);
    int c = blockIdx.x;     // 128
    int u = threadIdx.x;    // 256
    uint64_t* RA = (uint64_t*)g_RA;
    #pragma unroll 4
    for (int ch = 0; ch < 64; ++ch) {
        float v = g_HFT[(ch & 31)*32768 + c*256 + u] * inv;
        RA[ch*RCHP + (c+4)*RROW + 4 + u] = pack2(v);
    }
}

// ---------------- FUSED refine conv: tt+rr, 2 c-rows per thread, dup pairs ----------------
// grid = 256: cpair = bid>>2 (c0 = 2*cpair), osel = bid&3 (8 outs of each conv)
__global__ __launch_bounds__(256) void k_refconv(
    const float* __restrict__ Wt, const float* __restrict__ Wr,
    const float* __restrict__ Bt, const float* __restrict__ Br,
    int swap)
{
    const uint64_t* RIN  = (const uint64_t*)(swap ? g_RB : g_RA);
    uint64_t*       ROUT = (uint64_t*)(swap ? g_RA : g_RB);
    int cpair = blockIdx.x >> 2;
    int osel  = blockIdx.x & 3;
    int o0    = osel * 8;
    int c0    = cpair * 2;
    int u     = threadIdx.x;      // 256
    __shared__ float4 sw[2304];   // per-kh stage: [kw(9)][ci(64)][4 float4] = 36KB

    uint64_t accT0[4] = {0,0,0,0}, accR0[4] = {0,0,0,0};
    uint64_t accT1[4] = {0,0,0,0}, accR1[4] = {0,0,0,0};

    for (int kh = 0; kh < 9; ++kh) {
        __syncthreads();
        for (int i = threadIdx.x; i < 2304; i += 256) {
            int kwci = i >> 2, part = i & 3;
            int koff = (kh*9 + (kwci >> 6))*2048 + (kwci & 63)*32 + o0;
            const float* src = (part < 2) ? (Wt + koff + part*4)
                                          : (Wr + koff + (part-2)*4);
            sw[i] = *(const float4*)src;
        }
        __syncthreads();

        // c-guard pad rows: row index c0+kh in [0,135] always valid (zeros in pads)
        const uint64_t* xp0 = RIN + (c0+kh)*RROW + u;       // +4 pad merges with kw-4
        const uint64_t* xp1 = xp0 + RROW;
        for (int kw = 0; kw < 9; ++kw) {
            const ulonglong2* wp = (const ulonglong2*)(sw + kw*256);
            #pragma unroll 1
            for (int cg = 0; cg < 16; ++cg) {
                uint64_t x0[4], x1[4];
                #pragma unroll
                for (int j = 0; j < 4; ++j) {
                    x0[j] = xp0[kw + (cg*4+j)*RCHP];
                    x1[j] = xp1[kw + (cg*4+j)*RCHP];
                }
                #pragma unroll
                for (int j = 0; j < 4; ++j) {
                    int ci = cg*4 + j;
                    ulonglong2 t01 = wp[4*ci];
                    ulonglong2 t23 = wp[4*ci+1];
                    ulonglong2 r01 = wp[4*ci+2];
                    ulonglong2 r23 = wp[4*ci+3];
                    fma2(accT0[0], x0[j], t01.x); fma2(accT0[1], x0[j], t01.y);
                    fma2(accT0[2], x0[j], t23.x); fma2(accT0[3], x0[j], t23.y);
                    fma2(accR0[0], x0[j], r01.x); fma2(accR0[1], x0[j], r01.y);
                    fma2(accR0[2], x0[j], r23.x); fma2(accR0[3], x0[j], r23.y);
                    fma2(accT1[0], x1[j], t01.x); fma2(accT1[1], x1[j], t01.y);
                    fma2(accT1[2], x1[j], t23.x); fma2(accT1[3], x1[j], t23.y);
                    fma2(accR1[0], x1[j], r01.x); fma2(accR1[1], x1[j], r01.y);
                    fma2(accR1[2], x1[j], r23.x); fma2(accR1[3], x1[j], r23.y);
                }
            }
        }
    }
    #pragma unroll
    for (int pos = 0; pos < 2; ++pos) {
        const uint64_t* aT = pos ? accT1 : accT0;
        const uint64_t* aR = pos ? accR1 : accR0;
        int e = (c0 + pos + 4)*RROW + 4 + u;
        #pragma unroll
        for (int p = 0; p < 4; ++p) {
            float2 vt = unpack2(aT[p]);
            float2 vr = unpack2(aR[p]);
            float tv[2] = {vt.x, vt.y};
            float rv[2] = {vr.x, vr.y};
            #pragma unroll
            for (int s = 0; s < 2; ++s) {
                int k = o0 + 2*p + s;
                float t = dfh_tanh(tv[s] + __ldg(Bt + k));
                float rraw = rv[s] + __ldg(Br + k);
                float r = (rraw > 0.0f ? rraw : 0.0f)*0.98f + 0.02f*rraw;
                ROUT[k*RCHP + e]      = add2(pack2(t), RIN[k*RCHP + e]);
                ROUT[(32+k)*RCHP + e] = add2(pack2(r), RIN[(32+k)*RCHP + e]);
            }
        }
    }
}

// ---------------- final dense (96 -> 2) ----------------
__global__ void k_final(const float* __restrict__ dw, const float* __restrict__ db,
                        float* __restrict__ out)
{
    int c = blockIdx.x;     // 128
    int u = threadIdx.x;    // 256
    int hpos = c*256 + u;
    int re = ((c+4)*RROW + 4 + u)*2;     // float index of pair .x
    float fn = __uint_as_float(g_FN);
    float a0 = __ldg(db), a1 = __ldg(db+1);
    #pragma unroll 8
    for (int p = 0; p < 64; ++p) {
        float v = g_RA[p*RCHP*2 + re] * fn;
        a0 += v*__ldg(dw + 2*p);
        a1 += v*__ldg(dw + 2*p + 1);
    }
    #pragma unroll 8
    for (int q = 0; q < 32; ++q) {
        float v = g_HFT[q*32768 + hpos];
        a0 += v*__ldg(dw + 2*(64+q));
        a1 += v*__ldg(dw + 2*(64+q) + 1);
    }
    out[hpos*2]     = a0;
    out[hpos*2 + 1] = a1/fn;
}

// ---------------- launch ----------------
extern "C" void kernel_launch(void* const* d_in, const int* in_sizes, int n_in,
                              void* d_out, int out_size)
{
    const float* times    = (const float*)d_in[0];
    const float* times_in = (const float*)d_in[1];
    const float* inp_nc   = (const float*)d_in[2];
    const float* inp_c    = (const float*)d_in[3];
    const float* cdw  = (const float*)d_in[4];
    const float* cdb  = (const float*)d_in[5];
    const float* cwy1 = (const float*)d_in[6];
    const float* cby1 = (const float*)d_in[7];
    const float* cwy2 = (const float*)d_in[8];
    const float* cby2 = (const float*)d_in[9];
    const float* cwz0 = (const float*)d_in[10];
    const float* cbz0 = (const float*)d_in[11];
    const float* hdw  = (const float*)d_in[12];
    const float* hdb  = (const float*)d_in[13];
    const float* hwy1 = (const float*)d_in[14];
    const float* hby1 = (const float*)d_in[15];
    const float* hwy2 = (const float*)d_in[16];
    const float* hby2 = (const float*)d_in[17];
    const float* hwz0 = (const float*)d_in[18];
    const float* hbz0 = (const float*)d_in[19];
    const float* rwr  = (const float*)d_in[20];
    const float* rbr  = (const float*)d_in[21];
    const float* rwt  = (const float*)d_in[22];
    const float* rbt  = (const float*)d_in[23];
    const float* dw   = (const float*)d_in[24];
    const float* db   = (const float*)d_in[25];
    float* out = (float*)d_out;

    // ---- fidnet 1: H=256, W=128, XP2=160, GP2=136 ----
    k_zero3<<<512,256>>>();           // also resets g_barcnt
    k_dense1<<<256,128>>>(inp_nc, inp_c, times, times_in, cdw, cdb);
    k_wave_all<256,128,160,136><<<256,256>>>(cwy1, cby1, cwy2, cby2, cwz0, cbz0);

    // ---- spectral glue ----
    k_c1<<<dim3(256,16),128>>>();
    k_c2<<<dim3(128,16),128>>>(times);

    // ---- fidnet 2: H=128, W=256, XP2=288, GP2=264 ----
    k_zero3<<<512,256>>>();           // re-zero + reset barcnt
    k_dense2<<<128,256>>>(hdw, hdb);
    k_wave_all<128,256,288,264><<<256,256>>>(hwy1, hby1, hwy2, hby2, hwz0, hbz0);

    // ---- hout_ft ----
    k_stageD<<<dim3(128,32),256>>>();

    // ---- fnorm + refine ----
    k_fninit<<<1,1>>>();
    k_fnred<<<256,256>>>();
    k_zeroref<<<512,256>>>();
    k_refinit<<<128,256>>>();
    for (int i = 0; i < 4; ++i) {
        k_refconv<<<256,256>>>(rwt + i*165888, rwr + i*165888,
                               rbt + i*32, rbr + i*32, i & 1);
    }

    // ---- final dense + output ----
    k_final<<<128,256>>>(dw, db, out);
}

// round 11
// speedup vs baseline: 1.0212x; 1.0212x over previous
#include <cuda_runtime.h>
#include <math.h>
#include <stdint.h>

// ---------------- constants ----------------
#define NCc 128
#define NTc 256
#define RSTR 264          // refine padded row stride (4 zero guards each side)
#define RCH  33792        // 128*264 per refine channel

__device__ __constant__ int c_DILS[15] = {1,2,3,4,6,8,10,12,14,16,18,20,24,28,32};

// ---------------- scratch ----------------
__device__ float g_X[655360];     // activations [H][16][XS] (padded)
__device__ float g_SKIP[655360];  // skip accumulator
__device__ float g_G[278528];     // gated intermediate [H][8][GS] (padded)
__device__ float g_R2[524288];    // [f(16)][m(128)][t(256)]
__device__ float g_HINP[524288];  // [c(128)][f(16)][t(256)]
__device__ float g_HFT[1048576];  // [g(32)][c(128)][u(256)]
__device__ float g_RA[2162688];   // refine ping [ch(64)][c(128)][RSTR]
__device__ float g_RB[2162688];   // refine pong
__device__ unsigned g_FN;
__device__ unsigned g_barcnt;

__device__ __forceinline__ float dfh_tanh(float x){ return tanhf(x)*0.98f + 0.02f*x; }
__device__ __forceinline__ float dfh_sig (float x){ return 0.98f/(1.0f+expf(-x)) + 0.02f*x; }

// ---------------- packed f32x2 helpers ----------------
__device__ __forceinline__ void fma2(uint64_t &d, uint64_t a, uint64_t b){
    asm("fma.rn.f32x2 %0, %1, %2, %0;" : "+l"(d) : "l"(a), "l"(b));
}
__device__ __forceinline__ uint64_t pack2(float x){
    uint64_t r; asm("mov.b64 %0, {%1, %1};" : "=l"(r) : "f"(x)); return r;
}
__device__ __forceinline__ float2 unpack2(uint64_t v){
    float2 f; asm("mov.b64 {%0, %1}, %2;" : "=f"(f.x), "=f"(f.y) : "l"(v)); return f;
}

// ---------------- grid barrier (all gridDim.x blocks resident) ----------------
__device__ __forceinline__ void gridbar(unsigned &target)
{
    __syncthreads();
    target += gridDim.x;
    if (threadIdx.x == 0) {
        __threadfence();
        atomicAdd(&g_barcnt, 1u);
        while (*((volatile unsigned*)&g_barcnt) < target) { }
        __threadfence();
    }
    __syncthreads();
}

// ---------------- zero helpers ----------------
__global__ void k_zero3()
{
    if (blockIdx.x == 0 && threadIdx.x == 0) g_barcnt = 0u;
    int stride = gridDim.x*blockDim.x;
    for (int i = blockIdx.x*blockDim.x + threadIdx.x; i < 655360; i += stride) {
        g_X[i] = 0.0f; g_SKIP[i] = 0.0f;
        if (i < 278528) g_G[i] = 0.0f;
    }
}
__global__ void k_zeroref()
{
    int stride = gridDim.x*blockDim.x;
    for (int i = blockIdx.x*blockDim.x + threadIdx.x; i < 2162688; i += stride) {
        g_RA[i] = 0.0f; g_RB[i] = 0.0f;
    }
}

// ---------------- input dense (4->16) ----------------
__global__ void k_dense1(const float* __restrict__ inc, const float* __restrict__ icc,
                         const float* __restrict__ times, const float* __restrict__ tin,
                         const float* __restrict__ cw, const float* __restrict__ cb)
{
    int t = blockIdx.x, c = threadIdx.x;  // 256 x 128
    float i0 = inc[c*NTc + t];
    float i1 = icc[c*NTc + t];
    float i2 = times[t];
    float i3 = tin[c];
    #pragma unroll
    for (int o = 0; o < 16; ++o) {
        float v = i0*cw[o] + i1*cw[16+o] + i2*cw[32+o] + i3*cw[48+o] + cb[o];
        g_X[(t*16+o)*160 + c] = dfh_tanh(v);
    }
}

// ---------------- PERSISTENT wave stack: 128 blocks, full-width outputs ----------------
// Each thread owns ONE spatial position and ALL outputs.
template<int H, int W, int XS, int GS>
__global__ __launch_bounds__(256,1) void k_wave_all(
    const float* __restrict__ wy1a, const float* __restrict__ by1a,
    const float* __restrict__ wy2a, const float* __restrict__ by2a,
    const float* __restrict__ wza,  const float* __restrict__ bza)
{
    constexpr int CHUNKS = W >> 5;        // 4 (W=128) or 8 (W=256)
    constexpr int RPB    = 8 / CHUNKS;    // rows per block: 2 or 1
    __shared__ float4 sW[2560];           // 40KB (conv12: both convs; convz: first 1280)
    int tidx = threadIdx.x;
    int lane = tidx & 31, warp = tidx >> 5;
    int r = warp / CHUNKS, q = warp - r*CHUNKS;
    int w = (q << 5) + lane;
    int h = blockIdx.x * RPB + r;
    unsigned target = 0;

    for (int layer = 0; layer < 45; ++layer) {
        int dil = c_DILS[layer % 15];

        // ======== phase 1: gated conv pair (16ch -> 8+8 outs, all in this thread) ========
        {
            const float* w1g = wy1a + layer*5120;
            const float* w2g = wy2a + layer*5120;
            const float* b1  = by1a + layer*8;
            const float* b2  = by2a + layer*8;
            // stage: sW[0..1280) = conv1 [tap(40)][ci(16)][2xfloat4 outs0..7]
            //        sW[1280..2560) = conv2 same layout
            for (int i = tidx; i < 1280; i += 256) {
                int tap = i >> 5, rem = i & 31, ci = rem >> 1, part = rem & 1;
                sW[i]        = *(const float4*)(w1g + tap*128 + ci*8 + part*4);
                sW[1280 + i] = *(const float4*)(w2g + tap*128 + ci*8 + part*4);
            }
            __syncthreads();

            uint64_t a1[4] = {0,0,0,0};   // conv1 outs (pairs 01,23,45,67)
            uint64_t a2[4] = {0,0,0,0};   // conv2 outs

            for (int kh = 0; kh < 5; ++kh) {
                int hh = h + kh - 2;
                if ((unsigned)hh >= (unsigned)H) continue;
                const float* xrow = g_X + hh*16*XS;
                for (int kw = 0; kw < 8; ++kw) {
                    int cb0 = (q << 5) + kw*dil;
                    if (cb0 >= W) break;               // warp-uniform
                    const float* xp = xrow + cb0 + lane;
                    const ulonglong2* wp1 = (const ulonglong2*)(sW + (kh*8+kw)*32);
                    const ulonglong2* wp2 = (const ulonglong2*)(sW + 1280 + (kh*8+kw)*32);
                    float xs[16];
                    #pragma unroll
                    for (int ci = 0; ci < 16; ++ci) xs[ci] = xp[ci*XS];
                    #pragma unroll
                    for (int ci = 0; ci < 16; ++ci) {
                        uint64_t xv = pack2(xs[ci]);
                        ulonglong2 wA = wp1[2*ci], wB = wp1[2*ci+1];
                        ulonglong2 wC = wp2[2*ci], wD = wp2[2*ci+1];
                        fma2(a1[0], xv, wA.x); fma2(a1[1], xv, wA.y);
                        fma2(a1[2], xv, wB.x); fma2(a1[3], xv, wB.y);
                        fma2(a2[0], xv, wC.x); fma2(a2[1], xv, wC.y);
                        fma2(a2[2], xv, wD.x); fma2(a2[3], xv, wD.y);
                    }
                }
            }
            #pragma unroll
            for (int p = 0; p < 4; ++p) {
                float2 v1 = unpack2(a1[p]);
                float2 v2 = unpack2(a2[p]);
                int o0 = 2*p;
                float g0 = dfh_tanh(v1.x + __ldg(b1+o0))   * dfh_sig(v2.x + __ldg(b2+o0));
                float g1 = dfh_tanh(v1.y + __ldg(b1+o0+1)) * dfh_sig(v2.y + __ldg(b2+o0+1));
                g_G[(h*8+o0)*GS + w]   = g0;
                g_G[(h*8+o0+1)*GS + w] = g1;
            }
        }
        gridbar(target);

        // ======== phase 2: z conv (8ch -> all 16 outs) ========
        {
            const float* wzg = wza + layer*5120;
            const float* bz  = bza + layer*16;
            // stage: sW[0..1280) = [tap(40)][ci(8)][4xfloat4 outs0..15]
            for (int i = tidx; i < 1280; i += 256) {
                int tap = i >> 5, rem = i & 31, ci = rem >> 2, part = rem & 3;
                sW[i] = *(const float4*)(wzg + tap*128 + ci*16 + part*4);
            }
            __syncthreads();

            uint64_t az[8] = {0,0,0,0,0,0,0,0};   // 16 outs as 8 pairs

            for (int kh = 0; kh < 5; ++kh) {
                int hh = h + kh - 2;
                if ((unsigned)hh >= (unsigned)H) continue;
                const float* grow = g_G + hh*8*GS + w;
                #pragma unroll
                for (int kw = 0; kw < 8; ++kw) {
                    const float* xp = grow + kw;           // zero pad: no guard
                    const ulonglong2* wp = (const ulonglong2*)(sW + (kh*8+kw)*32);
                    float xs[8];
                    #pragma unroll
                    for (int ci = 0; ci < 8; ++ci) xs[ci] = xp[ci*GS];
                    #pragma unroll
                    for (int ci = 0; ci < 8; ++ci) {
                        uint64_t xv = pack2(xs[ci]);
                        ulonglong2 wA = wp[4*ci],   wB = wp[4*ci+1];
                        ulonglong2 wC = wp[4*ci+2], wD = wp[4*ci+3];
                        fma2(az[0], xv, wA.x); fma2(az[1], xv, wA.y);
                        fma2(az[2], xv, wB.x); fma2(az[3], xv, wB.y);
                        fma2(az[4], xv, wC.x); fma2(az[5], xv, wC.y);
                        fma2(az[6], xv, wD.x); fma2(az[7], xv, wD.y);
                    }
                }
            }
            #pragma unroll
            for (int p = 0; p < 8; ++p) {
                float2 v = unpack2(az[p]);
                int oo = 2*p;
                float z0 = v.x + __ldg(bz+oo);
                float z1 = v.y + __ldg(bz+oo+1);
                int idx0 = (h*16+oo)*XS + w;
                int idx1 = idx0 + XS;
                g_SKIP[idx0] += z0;  g_X[idx0] += z0;
                g_SKIP[idx1] += z1;  g_X[idx1] += z1;
            }
        }
        gridbar(target);
    }
}

// ---------------- stage C1 ----------------
__global__ void k_c1()
{
    int t = blockIdx.x, f = blockIdx.y;     // 256 x 16
    __shared__ float vr[64], vi[64], tc[128], ts[128];
    int tid = threadIdx.x;                  // 128
    if (tid < 64) {
        int k = tid;
        float cr = g_SKIP[(t*16+f)*160 + 2*k];
        float ci = g_SKIP[(t*16+f)*160 + 2*k+1];
        cr = dfh_tanh(cr); ci = dfh_tanh(ci);
        float s = ((k==0)?0.5f:1.0f) * ((k&1)?-1.0f:1.0f);
        vr[k] = s*cr; vi[k] = s*ci;
    }
    {
        float sv, cv; sincospif((float)tid * (1.0f/64.0f), &sv, &cv);
        tc[tid] = cv; ts[tid] = sv;
    }
    __syncthreads();
    int m = tid;
    float acc = 0.0f;
    #pragma unroll 8
    for (int k = 0; k < 64; ++k) {
        int j = (k*m) & 127;
        acc += vr[k]*tc[j] + vi[k]*ts[j];
    }
    g_R2[(f*128+m)*NTc + t] = acc;
}

// ---------------- stage C2 ----------------
__global__ void k_c2(const float* __restrict__ times)
{
    int m = blockIdx.x, f = blockIdx.y;     // 128 x 16
    __shared__ float v[256], tc[256], ts[256];
    int tid = threadIdx.x;                  // 128
    v[tid]       = g_R2[(f*128+m)*NTc + tid];
    v[tid+128]   = g_R2[(f*128+m)*NTc + tid + 128];
    {
        float sv, cv;
        sincospif((float)tid * (1.0f/128.0f), &sv, &cv);        tc[tid] = cv;      ts[tid] = sv;
        sincospif((float)(tid+128) * (1.0f/128.0f), &sv, &cv);  tc[tid+128] = cv;  ts[tid+128] = sv;
    }
    __syncthreads();
    int k = tid;
    float zm = (k==0) ? 1.0f : ((fabsf(times[2*k]) > 0.0f) ? 1.0f : 0.0f);
    float scale = zm * ((k&1)?-1.0f:1.0f) * (1.0f/128.0f);
    float ar = 0.0f, ai = 0.0f;
    #pragma unroll 8
    for (int t = 0; t < 256; ++t) {
        int j = (t*k) & 255;
        ar += v[t]*tc[j];
        ai += v[t]*ts[j];
    }
    g_HINP[(m*16+f)*NTc + 2*k]   = scale*ar;
    g_HINP[(m*16+f)*NTc + 2*k+1] = scale*ai;
}

// ---------------- dense2 (16->16) ----------------
__global__ void k_dense2(const float* __restrict__ hw, const float* __restrict__ hb)
{
    int c = blockIdx.x;       // 128
    int t = threadIdx.x;      // 256
    float in[16];
    #pragma unroll
    for (int f = 0; f < 16; ++f) in[f] = g_HINP[(c*16+f)*NTc + t];
    #pragma unroll
    for (int o = 0; o < 16; ++o) {
        float acc = hb[o];
        #pragma unroll
        for (int f = 0; f < 16; ++f) acc += in[f]*hw[f*16+o];
        g_X[(c*16+o)*288 + t] = dfh_tanh(acc);
    }
}

// ---------------- stage D ----------------
__global__ void k_stageD()
{
    int c = blockIdx.x, g = blockIdx.y;     // 128 x 32
    __shared__ float hr[128], hi[128], tc[256], ts[256];
    int tid = threadIdx.x;                  // 256
    if (tid < 128) {
        int j = tid;
        float v0, v1;
        if (g < 16) {
            float a = g_SKIP[(c*16+g)*288 + 2*j];   v0 = dfh_tanh(a);
            float b = g_SKIP[(c*16+g)*288 + 2*j+1]; v1 = dfh_tanh(b);
        } else {
            v0 = g_HINP[(c*16+(g-16))*NTc + 2*j];
            v1 = g_HINP[(c*16+(g-16))*NTc + 2*j+1];
        }
        float s = ((j==0)?0.5f:1.0f) * ((j&1)?-1.0f:1.0f);
        hr[j] = s*v0; hi[j] = s*v1;
    }
    {
        float sv, cv; sincospif((float)tid * (1.0f/128.0f), &sv, &cv);
        tc[tid] = cv; ts[tid] = sv;
    }
    __syncthreads();
    int u = tid;
    float acc = 0.0f;
    #pragma unroll 8
    for (int j = 0; j < 128; ++j) {
        int idx = (j*u) & 255;
        acc += hr[j]*tc[idx] + hi[j]*ts[idx];
    }
    g_HFT[(g*128+c)*NTc + u] = acc;
}

// ---------------- fnorm ----------------
__global__ void k_fninit(){ g_FN = 0u; }

__global__ void k_fnred()
{
    int stride = gridDim.x*blockDim.x;
    float mx = 0.0f;
    for (int i = blockIdx.x*blockDim.x + threadIdx.x; i < 1048576; i += stride)
        mx = fmaxf(mx, fabsf(g_HFT[i]));
    #pragma unroll
    for (int o = 16; o; o >>= 1) mx = fmaxf(mx, __shfl_xor_sync(0xFFFFFFFFu, mx, o));
    __shared__ float sm[8];
    int lane = threadIdx.x & 31, warp = threadIdx.x >> 5;
    if (lane == 0) sm[warp] = mx;
    __syncthreads();
    if (warp == 0) {
        mx = (lane < 8) ? sm[lane] : 0.0f;
        #pragma unroll
        for (int o = 4; o; o >>= 1) mx = fmaxf(mx, __shfl_xor_sync(0xFFFFFFFFu, mx, o));
        if (lane == 0) atomicMax(&g_FN, __float_as_uint(mx));
    }
}

__global__ void k_refinit()
{
    float inv = 1.0f/__uint_as_float(g_FN);
    int c = blockIdx.x;     // 128
    int u = threadIdx.x;    // 256
    #pragma unroll 4
    for (int ch = 0; ch < 64; ++ch)
        g_RA[ch*RCH + c*RSTR + 4 + u] = g_HFT[(ch & 31)*32768 + c*256 + u] * inv;
}

// ---------------- FUSED refine conv: tt (tanh) + rr (relu) with x-prefetch ----------------
__global__ __launch_bounds__(256) void k_refconv(
    const float* __restrict__ Wt, const float* __restrict__ Wr,
    const float* __restrict__ Bt, const float* __restrict__ Br,
    int swap)
{
    const float* RIN  = swap ? g_RB : g_RA;
    float*       ROUT = swap ? g_RA : g_RB;
    int c    = blockIdx.x >> 2;
    int osel = blockIdx.x & 3;
    int o0   = osel * 8;
    int u    = threadIdx.x;       // 256
    __shared__ float4 sw[2304];   // per-kh stage: [kw(9)][ci(64)][4 float4] = 36KB

    uint64_t accT[4] = {0,0,0,0};
    uint64_t accR[4] = {0,0,0,0};

    for (int kh = 0; kh < 9; ++kh) {
        __syncthreads();
        for (int i = threadIdx.x; i < 2304; i += 256) {
            int kwci = i >> 2, part = i & 3;
            int koff = (kh*9 + (kwci >> 6))*2048 + (kwci & 63)*32 + o0;
            const float* src = (part < 2) ? (Wt + koff + part*4)
                                          : (Wr + koff + (part-2)*4);
            sw[i] = *(const float4*)src;
        }
        __syncthreads();

        int cc = c + kh - 4;
        if ((unsigned)cc >= 128u) continue;      // block-uniform
        const float* rowp = RIN + cc*RSTR + u;
        for (int kw = 0; kw < 9; ++kw) {
            const float* xp = rowp + kw;
            const ulonglong2* wp = (const ulonglong2*)(sw + kw*256);
            #pragma unroll 1
            for (int cg = 0; cg < 8; ++cg) {
                float xs[8];
                #pragma unroll
                for (int j = 0; j < 8; ++j) xs[j] = __ldg(xp + (cg*8+j)*RCH);
                #pragma unroll
                for (int j = 0; j < 8; ++j) {
                    int ci = cg*8 + j;
                    uint64_t xv2 = pack2(xs[j]);
                    ulonglong2 t01 = wp[4*ci];
                    ulonglong2 t23 = wp[4*ci+1];
                    ulonglong2 r01 = wp[4*ci+2];
                    ulonglong2 r23 = wp[4*ci+3];
                    fma2(accT[0], xv2, t01.x); fma2(accT[1], xv2, t01.y);
                    fma2(accT[2], xv2, t23.x); fma2(accT[3], xv2, t23.y);
                    fma2(accR[0], xv2, r01.x); fma2(accR[1], xv2, r01.y);
                    fma2(accR[2], xv2, r23.x); fma2(accR[3], xv2, r23.y);
                }
            }
        }
    }
    int pos = c*RSTR + 4 + u;
    #pragma unroll
    for (int p = 0; p < 4; ++p) {
        float2 vt = unpack2(accT[p]);
        float2 vr = unpack2(accR[p]);
        float tv[2] = {vt.x, vt.y};
        float rv[2] = {vr.x, vr.y};
        #pragma unroll
        for (int s = 0; s < 2; ++s) {
            int k = o0 + 2*p + s;
            float t = dfh_tanh(tv[s] + __ldg(Bt + k));
            float rraw = rv[s] + __ldg(Br + k);
            float r = (rraw > 0.0f ? rraw : 0.0f)*0.98f + 0.02f*rraw;
            ROUT[k*RCH + pos]      = t + RIN[k*RCH + pos];
            ROUT[(32+k)*RCH + pos] = r + RIN[(32+k)*RCH + pos];
        }
    }
}

// ---------------- final dense (96 -> 2) ----------------
__global__ void k_final(const float* __restrict__ dw, const float* __restrict__ db,
                        float* __restrict__ out)
{
    int c = blockIdx.x;     // 128
    int u = threadIdx.x;    // 256
    int rpos = c*RSTR + 4 + u;
    int hpos = c*256 + u;
    float fn = __uint_as_float(g_FN);
    float a0 = __ldg(db), a1 = __ldg(db+1);
    #pragma unroll 8
    for (int p = 0; p < 64; ++p) {
        float v = g_RA[p*RCH + rpos] * fn;
        a0 += v*__ldg(dw + 2*p);
        a1 += v*__ldg(dw + 2*p + 1);
    }
    #pragma unroll 8
    for (int q = 0; q < 32; ++q) {
        float v = g_HFT[q*32768 + hpos];
        a0 += v*__ldg(dw + 2*(64+q));
        a1 += v*__ldg(dw + 2*(64+q) + 1);
    }
    out[hpos*2]     = a0;
    out[hpos*2 + 1] = a1/fn;
}

// ---------------- launch ----------------
extern "C" void kernel_launch(void* const* d_in, const int* in_sizes, int n_in,
                              void* d_out, int out_size)
{
    const float* times    = (const float*)d_in[0];
    const float* times_in = (const float*)d_in[1];
    const float* inp_nc   = (const float*)d_in[2];
    const float* inp_c    = (const float*)d_in[3];
    const float* cdw  = (const float*)d_in[4];
    const float* cdb  = (const float*)d_in[5];
    const float* cwy1 = (const float*)d_in[6];
    const float* cby1 = (const float*)d_in[7];
    const float* cwy2 = (const float*)d_in[8];
    const float* cby2 = (const float*)d_in[9];
    const float* cwz0 = (const float*)d_in[10];
    const float* cbz0 = (const float*)d_in[11];
    const float* hdw  = (const float*)d_in[12];
    const float* hdb  = (const float*)d_in[13];
    const float* hwy1 = (const float*)d_in[14];
    const float* hby1 = (const float*)d_in[15];
    const float* hwy2 = (const float*)d_in[16];
    const float* hby2 = (const float*)d_in[17];
    const float* hwz0 = (const float*)d_in[18];
    const float* hbz0 = (const float*)d_in[19];
    const float* rwr  = (const float*)d_in[20];
    const float* rbr  = (const float*)d_in[21];
    const float* rwt  = (const float*)d_in[22];
    const float* rbt  = (const float*)d_in[23];
    const float* dw   = (const float*)d_in[24];
    const float* db   = (const float*)d_in[25];
    float* out = (float*)d_out;

    // ---- fidnet 1: H=256, W=128, XS=160, GS=136 ----
    k_zero3<<<512,256>>>();           // also resets g_barcnt
    k_dense1<<<256,128>>>(inp_nc, inp_c, times, times_in, cdw, cdb);
    k_wave_all<256,128,160,136><<<128,256>>>(cwy1, cby1, cwy2, cby2, cwz0, cbz0);

    // ---- spectral glue ----
    k_c1<<<dim3(256,16),128>>>();
    k_c2<<<dim3(128,16),128>>>(times);

    // ---- fidnet 2: H=128, W=256, XS=288, GS=264 ----
    k_zero3<<<512,256>>>();           // resets g_barcnt again
    k_dense2<<<128,256>>>(hdw, hdb);
    k_wave_all<128,256,288,264><<<128,256>>>(hwy1, hby1, hwy2, hby2, hwz0, hbz0);

    // ---- hout_ft ----
    k_stageD<<<dim3(128,32),256>>>();

    // ---- fnorm + refine ----
    k_fninit<<<1,1>>>();
    k_fnred<<<256,256>>>();
    k_zeroref<<<512,256>>>();
    k_refinit<<<128,256>>>();
    for (int i = 0; i < 4; ++i) {
        k_refconv<<<512,256>>>(rwt + i*165888, rwr + i*165888,
                               rbt + i*32, rbr + i*32, i & 1);
    }

    // ---- final dense + output ----
    k_final<<<128,256>>>(dw, db, out);
}

// round 12
// speedup vs baseline: 1.1754x; 1.1510x over previous
#include <cuda_runtime.h>
#include <math.h>
#include <stdint.h>

// ---------------- constants ----------------
#define NCc 128
#define NTc 256
#define RSTR 264          // refine padded row stride (4 col guards each side)
#define RCHN 35904        // 136*264 floats per refine channel (4 row guards each side)

__device__ __constant__ int c_DILS[15] = {1,2,3,4,6,8,10,12,14,16,18,20,24,28,32};

// ---------------- scratch ----------------
__device__ float g_X[655360];     // activations [H][16][XS] (padded)
__device__ float g_SKIP[655360];  // skip accumulator
__device__ float g_G[278528];     // gated intermediate [H][8][GS] (padded)
__device__ float g_R2[524288];    // [f(16)][m(128)][t(256)]
__device__ float g_HINP[524288];  // [c(128)][f(16)][t(256)]
__device__ float g_HFT[1048576];  // [g(32)][c(128)][u(256)]
__device__ float g_RA[2297856];   // refine ping [ch(64)][row(136)][RSTR]
__device__ float g_RB[2297856];   // refine pong
__device__ unsigned g_FN;
__device__ unsigned g_barcnt;

__device__ __forceinline__ float dfh_tanh(float x){ return tanhf(x)*0.98f + 0.02f*x; }
__device__ __forceinline__ float dfh_sig (float x){ return 0.98f/(1.0f+expf(-x)) + 0.02f*x; }

// ---------------- packed f32x2 helpers ----------------
__device__ __forceinline__ void fma2(uint64_t &d, uint64_t a, uint64_t b){
    asm("fma.rn.f32x2 %0, %1, %2, %0;" : "+l"(d) : "l"(a), "l"(b));
}
__device__ __forceinline__ uint64_t pack2(float x){
    uint64_t r; asm("mov.b64 %0, {%1, %1};" : "=l"(r) : "f"(x)); return r;
}
__device__ __forceinline__ float2 unpack2(uint64_t v){
    float2 f; asm("mov.b64 {%0, %1}, %2;" : "=f"(f.x), "=f"(f.y) : "l"(v)); return f;
}

// ---------------- cp.async helpers ----------------
__device__ __forceinline__ uint32_t smem_u32(const void* p){
    uint32_t a;
    asm("{ .reg .u64 t; cvta.to.shared.u64 t, %1; cvt.u32.u64 %0, t; }" : "=r"(a) : "l"(p));
    return a;
}
__device__ __forceinline__ void cpasync16(uint32_t dst, const void* src){
    asm volatile("cp.async.cg.shared.global [%0], [%1], 16;" :: "r"(dst), "l"(src));
}
#define CP_COMMIT() asm volatile("cp.async.commit_group;")
#define CP_WAIT0()  asm volatile("cp.async.wait_group 0;")

// ---------------- grid barrier (all gridDim.x blocks resident) ----------------
__device__ __forceinline__ void gridbar(unsigned &target)
{
    __syncthreads();
    target += gridDim.x;
    if (threadIdx.x == 0) {
        __threadfence();
        atomicAdd(&g_barcnt, 1u);
        while (*((volatile unsigned*)&g_barcnt) < target) { }
        __threadfence();
    }
    __syncthreads();
}

// ---------------- zero helpers ----------------
__global__ void k_zero3()
{
    if (blockIdx.x == 0 && threadIdx.x == 0) g_barcnt = 0u;
    int stride = gridDim.x*blockDim.x;
    for (int i = blockIdx.x*blockDim.x + threadIdx.x; i < 655360; i += stride) {
        g_X[i] = 0.0f; g_SKIP[i] = 0.0f;
        if (i < 278528) g_G[i] = 0.0f;
    }
}
__global__ void k_zeroref()
{
    int stride = gridDim.x*blockDim.x;
    for (int i = blockIdx.x*blockDim.x + threadIdx.x; i < 2297856; i += stride) {
        g_RA[i] = 0.0f; g_RB[i] = 0.0f;
    }
}

// ---------------- input dense (4->16) ----------------
__global__ void k_dense1(const float* __restrict__ inc, const float* __restrict__ icc,
                         const float* __restrict__ times, const float* __restrict__ tin,
                         const float* __restrict__ cw, const float* __restrict__ cb)
{
    int t = blockIdx.x, c = threadIdx.x;  // 256 x 128
    float i0 = inc[c*NTc + t];
    float i1 = icc[c*NTc + t];
    float i2 = times[t];
    float i3 = tin[c];
    #pragma unroll
    for (int o = 0; o < 16; ++o) {
        float v = i0*cw[o] + i1*cw[16+o] + i2*cw[32+o] + i3*cw[48+o] + cb[o];
        g_X[(t*16+o)*160 + c] = dfh_tanh(v);
    }
}

// ---------------- PERSISTENT wave stack: cp.async double-buffered weights ----------------
// Dynamic smem: [0,2560) float4 = conv12 weights (w1 then w2); [2560,3840) = convz.
template<int H, int W, int XS, int GS>
__global__ __launch_bounds__(256,1) void k_wave_all(
    const float* __restrict__ wy1a, const float* __restrict__ by1a,
    const float* __restrict__ wy2a, const float* __restrict__ by2a,
    const float* __restrict__ wza,  const float* __restrict__ bza)
{
    constexpr int CHUNKS = W >> 5;        // 4 (W=128) or 8 (W=256)
    constexpr int RPB    = 8 / CHUNKS;    // rows per block
    extern __shared__ float4 sDyn[];
    float4* sC = sDyn;            // conv12 buffer (2560 float4)
    float4* sZ = sDyn + 2560;     // convz buffer (1280 float4)
    uint32_t sCa = smem_u32(sC);
    uint32_t sZa = smem_u32(sZ);
    int tidx = threadIdx.x;
    int lane = tidx & 31, warp = tidx >> 5;
    int r = warp / CHUNKS, q = warp - r*CHUNKS;
    int w = (q << 5) + lane;
    int h = blockIdx.x * RPB + r;
    unsigned target = 0;

    // preload layer-0 conv12 weights
    {
        const float4* s1 = (const float4*)wy1a;
        const float4* s2 = (const float4*)wy2a;
        for (int i = tidx; i < 1280; i += 256) {
            cpasync16(sCa + i*16, s1 + i);
            cpasync16(sCa + (1280+i)*16, s2 + i);
        }
        CP_COMMIT(); CP_WAIT0();
    }
    __syncthreads();

    for (int layer = 0; layer < 45; ++layer) {
        int dil = c_DILS[layer % 15];

        // prefetch this layer's convz weights into sZ (consumed in phase 2)
        {
            const float4* sz = (const float4*)(wza + layer*5120);
            for (int i = tidx; i < 1280; i += 256)
                cpasync16(sZa + i*16, sz + i);
            CP_COMMIT();
        }

        // ======== phase 1: gated conv pair (16ch -> 8+8 outs) from sC ========
        {
            const float* b1 = by1a + layer*8;
            const float* b2 = by2a + layer*8;

            uint64_t a1[4] = {0,0,0,0};
            uint64_t a2[4] = {0,0,0,0};

            for (int kh = 0; kh < 5; ++kh) {
                int hh = h + kh - 2;
                if ((unsigned)hh >= (unsigned)H) continue;
                const float* xrow = g_X + hh*16*XS;
                for (int kw = 0; kw < 8; ++kw) {
                    int cb0 = (q << 5) + kw*dil;
                    if (cb0 >= W) break;               // warp-uniform
                    const float* xp = xrow + cb0 + lane;
                    const ulonglong2* wp1 = (const ulonglong2*)(sC + (kh*8+kw)*32);
                    const ulonglong2* wp2 = (const ulonglong2*)(sC + 1280 + (kh*8+kw)*32);
                    float xs[16];
                    #pragma unroll
                    for (int ci = 0; ci < 16; ++ci) xs[ci] = xp[ci*XS];
                    #pragma unroll
                    for (int ci = 0; ci < 16; ++ci) {
                        uint64_t xv = pack2(xs[ci]);
                        ulonglong2 wA = wp1[2*ci], wB = wp1[2*ci+1];
                        ulonglong2 wC = wp2[2*ci], wD = wp2[2*ci+1];
                        fma2(a1[0], xv, wA.x); fma2(a1[1], xv, wA.y);
                        fma2(a1[2], xv, wB.x); fma2(a1[3], xv, wB.y);
                        fma2(a2[0], xv, wC.x); fma2(a2[1], xv, wC.y);
                        fma2(a2[2], xv, wD.x); fma2(a2[3], xv, wD.y);
                    }
                }
            }
            #pragma unroll
            for (int p = 0; p < 4; ++p) {
                float2 v1 = unpack2(a1[p]);
                float2 v2 = unpack2(a2[p]);
                int o0 = 2*p;
                float g0 = dfh_tanh(v1.x + __ldg(b1+o0))   * dfh_sig(v2.x + __ldg(b2+o0));
                float g1 = dfh_tanh(v1.y + __ldg(b1+o0+1)) * dfh_sig(v2.y + __ldg(b2+o0+1));
                g_G[(h*8+o0)*GS + w]   = g0;
                g_G[(h*8+o0+1)*GS + w] = g1;
            }
        }
        gridbar(target);
        CP_WAIT0();          // convz weights landed
        __syncthreads();

        // prefetch NEXT layer's conv12 weights into sC (phase 1 done reading it)
        if (layer + 1 < 45) {
            const float4* s1 = (const float4*)(wy1a + (layer+1)*5120);
            const float4* s2 = (const float4*)(wy2a + (layer+1)*5120);
            for (int i = tidx; i < 1280; i += 256) {
                cpasync16(sCa + i*16, s1 + i);
                cpasync16(sCa + (1280+i)*16, s2 + i);
            }
            CP_COMMIT();
        }

        // ======== phase 2: z conv (8ch -> all 16 outs) from sZ ========
        {
            const float* bz = bza + layer*16;
            uint64_t az[8] = {0,0,0,0,0,0,0,0};

            for (int kh = 0; kh < 5; ++kh) {
                int hh = h + kh - 2;
                if ((unsigned)hh >= (unsigned)H) continue;
                const float* grow = g_G + hh*8*GS + w;
                #pragma unroll
                for (int kw = 0; kw < 8; ++kw) {
                    const float* xp = grow + kw;           // zero pad: no guard
                    const ulonglong2* wp = (const ulonglong2*)(sZ + (kh*8+kw)*32);
                    float xs[8];
                    #pragma unroll
                    for (int ci = 0; ci < 8; ++ci) xs[ci] = xp[ci*GS];
                    #pragma unroll
                    for (int ci = 0; ci < 8; ++ci) {
                        uint64_t xv = pack2(xs[ci]);
                        ulonglong2 wA = wp[4*ci],   wB = wp[4*ci+1];
                        ulonglong2 wC = wp[4*ci+2], wD = wp[4*ci+3];
                        fma2(az[0], xv, wA.x); fma2(az[1], xv, wA.y);
                        fma2(az[2], xv, wB.x); fma2(az[3], xv, wB.y);
                        fma2(az[4], xv, wC.x); fma2(az[5], xv, wC.y);
                        fma2(az[6], xv, wD.x); fma2(az[7], xv, wD.y);
                    }
                }
            }
            #pragma unroll
            for (int p = 0; p < 8; ++p) {
                float2 v = unpack2(az[p]);
                int oo = 2*p;
                float z0 = v.x + __ldg(bz+oo);
                float z1 = v.y + __ldg(bz+oo+1);
                int idx0 = (h*16+oo)*XS + w;
                int idx1 = idx0 + XS;
                g_SKIP[idx0] += z0;  g_X[idx0] += z0;
                g_SKIP[idx1] += z1;  g_X[idx1] += z1;
            }
        }
        gridbar(target);
        CP_WAIT0();          // next conv12 weights landed
        __syncthreads();
    }
}

// ---------------- stage C1 ----------------
__global__ void k_c1()
{
    int t = blockIdx.x, f = blockIdx.y;     // 256 x 16
    __shared__ float vr[64], vi[64], tc[128], ts[128];
    int tid = threadIdx.x;                  // 128
    if (tid < 64) {
        int k = tid;
        float cr = g_SKIP[(t*16+f)*160 + 2*k];
        float ci = g_SKIP[(t*16+f)*160 + 2*k+1];
        cr = dfh_tanh(cr); ci = dfh_tanh(ci);
        float s = ((k==0)?0.5f:1.0f) * ((k&1)?-1.0f:1.0f);
        vr[k] = s*cr; vi[k] = s*ci;
    }
    {
        float sv, cv; sincospif((float)tid * (1.0f/64.0f), &sv, &cv);
        tc[tid] = cv; ts[tid] = sv;
    }
    __syncthreads();
    int m = tid;
    float acc = 0.0f;
    #pragma unroll 8
    for (int k = 0; k < 64; ++k) {
        int j = (k*m) & 127;
        acc += vr[k]*tc[j] + vi[k]*ts[j];
    }
    g_R2[(f*128+m)*NTc + t] = acc;
}

// ---------------- stage C2 ----------------
__global__ void k_c2(const float* __restrict__ times)
{
    int m = blockIdx.x, f = blockIdx.y;     // 128 x 16
    __shared__ float v[256], tc[256], ts[256];
    int tid = threadIdx.x;                  // 128
    v[tid]       = g_R2[(f*128+m)*NTc + tid];
    v[tid+128]   = g_R2[(f*128+m)*NTc + tid + 128];
    {
        float sv, cv;
        sincospif((float)tid * (1.0f/128.0f), &sv, &cv);        tc[tid] = cv;      ts[tid] = sv;
        sincospif((float)(tid+128) * (1.0f/128.0f), &sv, &cv);  tc[tid+128] = cv;  ts[tid+128] = sv;
    }
    __syncthreads();
    int k = tid;
    float zm = (k==0) ? 1.0f : ((fabsf(times[2*k]) > 0.0f) ? 1.0f : 0.0f);
    float scale = zm * ((k&1)?-1.0f:1.0f) * (1.0f/128.0f);
    float ar = 0.0f, ai = 0.0f;
    #pragma unroll 8
    for (int t = 0; t < 256; ++t) {
        int j = (t*k) & 255;
        ar += v[t]*tc[j];
        ai += v[t]*ts[j];
    }
    g_HINP[(m*16+f)*NTc + 2*k]   = scale*ar;
    g_HINP[(m*16+f)*NTc + 2*k+1] = scale*ai;
}

// ---------------- dense2 (16->16) ----------------
__global__ void k_dense2(const float* __restrict__ hw, const float* __restrict__ hb)
{
    int c = blockIdx.x;       // 128
    int t = threadIdx.x;      // 256
    float in[16];
    #pragma unroll
    for (int f = 0; f < 16; ++f) in[f] = g_HINP[(c*16+f)*NTc + t];
    #pragma unroll
    for (int o = 0; o < 16; ++o) {
        float acc = hb[o];
        #pragma unroll
        for (int f = 0; f < 16; ++f) acc += in[f]*hw[f*16+o];
        g_X[(c*16+o)*288 + t] = dfh_tanh(acc);
    }
}

// ---------------- stage D ----------------
__global__ void k_stageD()
{
    int c = blockIdx.x, g = blockIdx.y;     // 128 x 32
    __shared__ float hr[128], hi[128], tc[256], ts[256];
    int tid = threadIdx.x;                  // 256
    if (tid < 128) {
        int j = tid;
        float v0, v1;
        if (g < 16) {
            float a = g_SKIP[(c*16+g)*288 + 2*j];   v0 = dfh_tanh(a);
            float b = g_SKIP[(c*16+g)*288 + 2*j+1]; v1 = dfh_tanh(b);
        } else {
            v0 = g_HINP[(c*16+(g-16))*NTc + 2*j];
            v1 = g_HINP[(c*16+(g-16))*NTc + 2*j+1];
        }
        float s = ((j==0)?0.5f:1.0f) * ((j&1)?-1.0f:1.0f);
        hr[j] = s*v0; hi[j] = s*v1;
    }
    {
        float sv, cv; sincospif((float)tid * (1.0f/128.0f), &sv, &cv);
        tc[tid] = cv; ts[tid] = sv;
    }
    __syncthreads();
    int u = tid;
    float acc = 0.0f;
    #pragma unroll 8
    for (int j = 0; j < 128; ++j) {
        int idx = (j*u) & 255;
        acc += hr[j]*tc[idx] + hi[j]*ts[idx];
    }
    g_HFT[(g*128+c)*NTc + u] = acc;
}

// ---------------- fnorm ----------------
__global__ void k_fninit(){ g_FN = 0u; }

__global__ void k_fnred()
{
    int stride = gridDim.x*blockDim.x;
    float mx = 0.0f;
    for (int i = blockIdx.x*blockDim.x + threadIdx.x; i < 1048576; i += stride)
        mx = fmaxf(mx, fabsf(g_HFT[i]));
    #pragma unroll
    for (int o = 16; o; o >>= 1) mx = fmaxf(mx, __shfl_xor_sync(0xFFFFFFFFu, mx, o));
    __shared__ float sm[8];
    int lane = threadIdx.x & 31, warp = threadIdx.x >> 5;
    if (lane == 0) sm[warp] = mx;
    __syncthreads();
    if (warp == 0) {
        mx = (lane < 8) ? sm[lane] : 0.0f;
        #pragma unroll
        for (int o = 4; o; o >>= 1) mx = fmaxf(mx, __shfl_xor_sync(0xFFFFFFFFu, mx, o));
        if (lane == 0) atomicMax(&g_FN, __float_as_uint(mx));
    }
}

__global__ void k_refinit()
{
    float inv = 1.0f/__uint_as_float(g_FN);
    int c = blockIdx.x;     // 128
    int u = threadIdx.x;    // 256
    #pragma unroll 4
    for (int ch = 0; ch < 64; ++ch)
        g_RA[ch*RCHN + (c+4)*RSTR + 4 + u] = g_HFT[(ch & 31)*32768 + c*256 + u] * inv;
}

// ---------------- FUSED refine conv: tt+rr, 2 c-rows per thread ----------------
// grid = 256: cpair = bid>>2 (c0 = 2*cpair), osel = bid&3 (8 outs of each conv)
__global__ __launch_bounds__(256) void k_refconv(
    const float* __restrict__ Wt, const float* __restrict__ Wr,
    const float* __restrict__ Bt, const float* __restrict__ Br,
    int swap)
{
    const float* RIN  = swap ? g_RB : g_RA;
    float*       ROUT = swap ? g_RA : g_RB;
    int cpair = blockIdx.x >> 2;   // 0..63
    int osel  = blockIdx.x & 3;
    int o0    = osel * 8;
    int c0    = cpair * 2;
    int u     = threadIdx.x;       // 256
    __shared__ float4 sw[2304];    // per-kh stage: [kw(9)][ci(64)][4 float4] = 36KB

    uint64_t accT0[4] = {0,0,0,0}, accR0[4] = {0,0,0,0};
    uint64_t accT1[4] = {0,0,0,0}, accR1[4] = {0,0,0,0};

    for (int kh = 0; kh < 9; ++kh) {
        __syncthreads();
        for (int i = threadIdx.x; i < 2304; i += 256) {
            int kwci = i >> 2, part = i & 3;
            int koff = (kh*9 + (kwci >> 6))*2048 + (kwci & 63)*32 + o0;
            const float* src = (part < 2) ? (Wt + koff + part*4)
                                          : (Wr + koff + (part-2)*4);
            sw[i] = *(const float4*)src;
        }
        __syncthreads();

        // row c0+kh in [0,134] always valid (4 zero guard rows each side)
        const float* xr0 = RIN + (c0+kh)*RSTR + u;
        const float* xr1 = xr0 + RSTR;
        for (int kw = 0; kw < 9; ++kw) {
            const ulonglong2* wp = (const ulonglong2*)(sw + kw*256);
            #pragma unroll 1
            for (int cg = 0; cg < 16; ++cg) {
                float xs0[4], xs1[4];
                #pragma unroll
                for (int j = 0; j < 4; ++j) {
                    xs0[j] = __ldg(xr0 + kw + (cg*4+j)*RCHN);
                    xs1[j] = __ldg(xr1 + kw + (cg*4+j)*RCHN);
                }
                #pragma unroll
                for (int j = 0; j < 4; ++j) {
                    int ci = cg*4 + j;
                    uint64_t x0 = pack2(xs0[j]);
                    uint64_t x1 = pack2(xs1[j]);
                    ulonglong2 t01 = wp[4*ci];
                    ulonglong2 t23 = wp[4*ci+1];
                    ulonglong2 r01 = wp[4*ci+2];
                    ulonglong2 r23 = wp[4*ci+3];
                    fma2(accT0[0], x0, t01.x); fma2(accT0[1], x0, t01.y);
                    fma2(accT0[2], x0, t23.x); fma2(accT0[3], x0, t23.y);
                    fma2(accR0[0], x0, r01.x); fma2(accR0[1], x0, r01.y);
                    fma2(accR0[2], x0, r23.x); fma2(accR0[3], x0, r23.y);
                    fma2(accT1[0], x1, t01.x); fma2(accT1[1], x1, t01.y);
                    fma2(accT1[2], x1, t23.x); fma2(accT1[3], x1, t23.y);
                    fma2(accR1[0], x1, r01.x); fma2(accR1[1], x1, r01.y);
                    fma2(accR1[2], x1, r23.x); fma2(accR1[3], x1, r23.y);
                }
            }
        }
    }
    // epilogue row 0
    {
        int e = (c0+4)*RSTR + 4 + u;
        #pragma unroll
        for (int p = 0; p < 4; ++p) {
            float2 vt = unpack2(accT0[p]);
            float2 vr = unpack2(accR0[p]);
            float tv[2] = {vt.x, vt.y};
            float rv[2] = {vr.x, vr.y};
            #pragma unroll
            for (int s = 0; s < 2; ++s) {
                int k = o0 + 2*p + s;
                float t = dfh_tanh(tv[s] + __ldg(Bt + k));
                float rraw = rv[s] + __ldg(Br + k);
                float rr = (rraw > 0.0f ? rraw : 0.0f)*0.98f + 0.02f*rraw;
                ROUT[k*RCHN + e]      = t  + RIN[k*RCHN + e];
                ROUT[(32+k)*RCHN + e] = rr + RIN[(32+k)*RCHN + e];
            }
        }
    }
    // epilogue row 1
    {
        int e = (c0+5)*RSTR + 4 + u;
        #pragma unroll
        for (int p = 0; p < 4; ++p) {
            float2 vt = unpack2(accT1[p]);
            float2 vr = unpack2(accR1[p]);
            float tv[2] = {vt.x, vt.y};
            float rv[2] = {vr.x, vr.y};
            #pragma unroll
            for (int s = 0; s < 2; ++s) {
                int k = o0 + 2*p + s;
                float t = dfh_tanh(tv[s] + __ldg(Bt + k));
                float rraw = rv[s] + __ldg(Br + k);
                float rr = (rraw > 0.0f ? rraw : 0.0f)*0.98f + 0.02f*rraw;
                ROUT[k*RCHN + e]      = t  + RIN[k*RCHN + e];
                ROUT[(32+k)*RCHN + e] = rr + RIN[(32+k)*RCHN + e];
            }
        }
    }
}

// ---------------- final dense (96 -> 2) ----------------
__global__ void k_final(const float* __restrict__ dw, const float* __restrict__ db,
                        float* __restrict__ out)
{
    int c = blockIdx.x;     // 128
    int u = threadIdx.x;    // 256
    int rpos = (c+4)*RSTR + 4 + u;
    int hpos = c*256 + u;
    float fn = __uint_as_float(g_FN);
    float a0 = __ldg(db), a1 = __ldg(db+1);
    #pragma unroll 8
    for (int p = 0; p < 64; ++p) {
        float v = g_RA[p*RCHN + rpos] * fn;
        a0 += v*__ldg(dw + 2*p);
        a1 += v*__ldg(dw + 2*p + 1);
    }
    #pragma unroll 8
    for (int q = 0; q < 32; ++q) {
        float v = g_HFT[q*32768 + hpos];
        a0 += v*__ldg(dw + 2*(64+q));
        a1 += v*__ldg(dw + 2*(64+q) + 1);
    }
    out[hpos*2]     = a0;
    out[hpos*2 + 1] = a1/fn;
}

// ---------------- launch ----------------
extern "C" void kernel_launch(void* const* d_in, const int* in_sizes, int n_in,
                              void* d_out, int out_size)
{
    const float* times    = (const float*)d_in[0];
    const float* times_in = (const float*)d_in[1];
    const float* inp_nc   = (const float*)d_in[2];
    const float* inp_c    = (const float*)d_in[3];
    const float* cdw  = (const float*)d_in[4];
    const float* cdb  = (const float*)d_in[5];
    const float* cwy1 = (const float*)d_in[6];
    const float* cby1 = (const float*)d_in[7];
    const float* cwy2 = (const float*)d_in[8];
    const float* cby2 = (const float*)d_in[9];
    const float* cwz0 = (const float*)d_in[10];
    const float* cbz0 = (const float*)d_in[11];
    const float* hdw  = (const float*)d_in[12];
    const float* hdb  = (const float*)d_in[13];
    const float* hwy1 = (const float*)d_in[14];
    const float* hby1 = (const float*)d_in[15];
    const float* hwy2 = (const float*)d_in[16];
    const float* hby2 = (const float*)d_in[17];
    const float* hwz0 = (const float*)d_in[18];
    const float* hbz0 = (const float*)d_in[19];
    const float* rwr  = (const float*)d_in[20];
    const float* rbr  = (const float*)d_in[21];
    const float* rwt  = (const float*)d_in[22];
    const float* rbt  = (const float*)d_in[23];
    const float* dw   = (const float*)d_in[24];
    const float* db   = (const float*)d_in[25];
    float* out = (float*)d_out;

    // dynamic smem opt-in (idempotent; not a stream op, capture-safe)
    cudaFuncSetAttribute(k_wave_all<256,128,160,136>,
                         cudaFuncAttributeMaxDynamicSharedMemorySize, 61440);
    cudaFuncSetAttribute(k_wave_all<128,256,288,264>,
                         cudaFuncAttributeMaxDynamicSharedMemorySize, 61440);

    // ---- fidnet 1: H=256, W=128, XS=160, GS=136 ----
    k_zero3<<<512,256>>>();           // also resets g_barcnt
    k_dense1<<<256,128>>>(inp_nc, inp_c, times, times_in, cdw, cdb);
    k_wave_all<256,128,160,136><<<128,256,61440>>>(cwy1, cby1, cwy2, cby2, cwz0, cbz0);

    // ---- spectral glue ----
    k_c1<<<dim3(256,16),128>>>();
    k_c2<<<dim3(128,16),128>>>(times);

    // ---- fidnet 2: H=128, W=256, XS=288, GS=264 ----
    k_zero3<<<512,256>>>();           // resets g_barcnt again
    k_dense2<<<128,256>>>(hdw, hdb);
    k_wave_all<128,256,288,264><<<128,256,61440>>>(hwy1, hby1, hwy2, hby2, hwz0, hbz0);

    // ---- hout_ft ----
    k_stageD<<<dim3(128,32),256>>>();

    // ---- fnorm + refine ----
    k_fninit<<<1,1>>>();
    k_fnred<<<256,256>>>();
    k_zeroref<<<512,256>>>();
    k_refinit<<<128,256>>>();
    for (int i = 0; i < 4; ++i) {
        k_refconv<<<256,256>>>(rwt + i*165888, rwr + i*165888,
                               rbt + i*32, rbr + i*32, i & 1);
    }

    // ---- final dense + output ----
    k_final<<<128,256>>>(dw, db, out);
}